// round 14
// baseline (speedup 1.0000x reference)
#include <cuda_runtime.h>
#include <math.h>

#ifndef M_PI
#define M_PI 3.14159265358979323846
#endif

#define MROWS 4096
#define ROWSTRIDE 74
#define GRP 128
#define NGRP 32
#define NTILES 528          // 32*33/2 pair tiles == grid size
#define NROWBLK 512         // blocks that do rows work (8 rows each)
#define TABN 1024
#define FULLMASK 0xffffffffu

__device__ float2 g_zs[MROWS];
__device__ double g_pairp[NTILES];
__device__ double g_rowp[NROWBLK][4];   // rec, ce, b, den
__device__ unsigned g_bar;              // monotonic ticket barrier
__device__ unsigned g_done;             // monotonic finalize counter

// ---- small branch: poly in s^2, coeffs folded with (1/56.25)^k ----
#define P56 56.25
#define BC0 ((float)(3.5156229 / P56))
#define BC1 ((float)(3.0899424 / (P56 * P56)))
#define BC2 ((float)(1.2067492 / (P56 * P56 * P56)))
#define BC3 ((float)(0.2659732 / (P56 * P56 * P56 * P56)))
#define BC4 ((float)(0.0360768 / (P56 * P56 * P56 * P56 * P56)))
#define BC5 ((float)(0.0045813 / (P56 * P56 * P56 * P56 * P56 * P56)))
// ---- large branch: coeffs folded with sqrt(2)*7.5^k, poly in 1/s ----
#define SQ2 1.4142135623730951
#define QD0 ((float)(0.39894228 * SQ2))
#define QD1 ((float)(0.01328592 * SQ2 * 7.5))
#define QD2 ((float)(0.00225319 * SQ2 * 56.25))
#define QD3 ((float)(-0.00157565 * SQ2 * 421.875))
#define QD4 ((float)(0.0091628 * SQ2 * 3164.0625))
#define QD5 ((float)(-0.02057706 * SQ2 * 23730.46875))
#define QD6 ((float)(0.02635537 * SQ2 * 177978.515625))
#define QD7 ((float)(-0.01647633 * SQ2 * 1334838.8671875))
#define QD8 ((float)(0.00392377 * SQ2 * 10011291.50390625))

__device__ __forceinline__ float rsqa(float x) {
    float r; asm("rsqrt.approx.f32 %0,%1;" : "=f"(r) : "f"(x)); return r;
}

// exact reference phi (rows / finalize / LUT build)
__device__ __forceinline__ float phi_sel(float s, float K1) {
    float s2 = s * s;
    float p = fmaf(s2, BC5, BC4);
    p = fmaf(s2, p, BC3);
    p = fmaf(s2, p, BC2);
    p = fmaf(s2, p, BC1);
    p = fmaf(s2, p, BC0);
    p = fmaf(s2, p, 1.0f);
    float e  = __expf(-0.5f * s);
    float sv = fmaf(p, e, K1);
    float r  = rsqrtf(s);
    float iv = r * r;
    float q = fmaf(iv, QD8, QD7);
    q = fmaf(iv, q, QD6);
    q = fmaf(iv, q, QD5);
    q = fmaf(iv, q, QD4);
    q = fmaf(iv, q, QD3);
    q = fmaf(iv, q, QD2);
    q = fmaf(iv, q, QD1);
    q = fmaf(iv, q, QD0);
    float bv = r * q;
    return (s <= 7.5f) ? sv : bv;
}

__device__ __forceinline__ float phi_of_t(float t, float K1) {
    if (t <= 0.f) return 0.f;
    double td = (double)t;
    double sd = 1.0 / (td * td) - 1.0;
    if (sd < 0.0) sd = 0.0;
    return phi_sel((float)sd, K1);
}

__device__ __forceinline__ float ftanh(float x) {
    float e = __expf(2.f * x);
    return 1.f - __fdividef(2.f, e + 1.f);
}
__device__ __forceinline__ float wsum(float v) {
    #pragma unroll
    for (int o = 16; o; o >>= 1) v += __shfl_xor_sync(FULLMASK, v, o);
    return v;
}
__device__ __forceinline__ double wsumd(double v) {
    #pragma unroll
    for (int o = 16; o; o >>= 1) v += __shfl_xor_sync(FULLMASK, v, o);
    return v;
}
__device__ __forceinline__ float wmax(float v) {
    #pragma unroll
    for (int o = 16; o; o >>= 1) v = fmaxf(v, __shfl_xor_sync(FULLMASK, v, o));
    return v;
}

struct RowsSmem {
    float We1[2048], Wd3[2048], We2[512], Wd2[512], We3[32], Wd1[32];
    float Be1[32], Be2[16], Be3[2], Bd1[16], Bd2[32], Bd3[64];
    float ClsC[10], Inv2v[10], Bcoef[10], Binv[10], Mu[20];
    float tau[8][64], h1[8][32], h2[8][16], d1[8][16], d2[8][32];
};
struct PairSmem {
    float2 zi[GRP], zj[GRP];
};

__global__ void __launch_bounds__(256) segma_one(
    const float* __restrict__ bd,
    const float* __restrict__ We1, const float* __restrict__ be1,
    const float* __restrict__ We2, const float* __restrict__ be2,
    const float* __restrict__ We3, const float* __restrict__ be3,
    const float* __restrict__ Wd1, const float* __restrict__ bd1,
    const float* __restrict__ Wd2, const float* __restrict__ bd2,
    const float* __restrict__ Wd3, const float* __restrict__ bd3,
    const float* __restrict__ means, const float* __restrict__ vars,
    const float* __restrict__ probs, float* __restrict__ out,
    float K1, float rsc, float gam, double phi0, double scaleA)
{
    __shared__ union { RowsSmem r; PairSmem p; } U;
    __shared__ float sTab[TABN + 1];
    __shared__ double sRed[8];
    __shared__ double sRed4[8][4];
    __shared__ bool sLast;

    const int tid = threadIdx.x;
    const int w   = tid >> 5;
    const int l   = tid & 31;
    const int bid = blockIdx.x;

    // ---- build phi LUT locally (independent of rows) ----
    for (int e = tid; e <= TABN; e += 256) {
        float t = (float)e / (float)TABN;
        sTab[e] = phi_of_t(t, K1);
    }

    // ================= phase 1: rows (blocks 0..511, 1 row/warp) ==========
    if (bid < NROWBLK) {
        for (int i = tid; i < 2048; i += 256) { U.r.We1[i] = We1[i]; U.r.Wd3[i] = Wd3[i]; }
        for (int i = tid; i < 512;  i += 256) { U.r.We2[i] = We2[i]; U.r.Wd2[i] = Wd2[i]; }
        if (tid < 32) { U.r.We3[tid] = We3[tid]; U.r.Wd1[tid] = Wd1[tid]; U.r.Be1[tid] = be1[tid]; U.r.Bd2[tid] = bd2[tid]; }
        if (tid < 16) { U.r.Be2[tid] = be2[tid]; U.r.Bd1[tid] = bd1[tid]; }
        if (tid < 2)  { U.r.Be3[tid] = be3[tid]; }
        if (tid < 64) { U.r.Bd3[tid] = bd3[tid]; }
        if (tid < 20) U.r.Mu[tid] = means[tid];
        if (tid < 10) {
            float v = vars[tid], p = probs[tid];
            U.r.ClsC[tid]  = logf(p) - logf(2.f * (float)M_PI * v);
            U.r.Inv2v[tid] = 0.5f / v;
            float vp2g = v + 2.f * gam;
            U.r.Bcoef[tid] = 2.f * p / ((float)MROWS * sqrtf(2.f * (float)M_PI * vp2g));
            U.r.Binv[tid]  = 0.5f / vp2g;
        }
        __syncthreads();

        float rec_acc = 0.f, ce_acc = 0.f, b_acc = 0.f, den_acc = 0.f;
        {
            int row = bid * 8 + w;
            const float* rowp = bd + row * ROWSTRIDE;
            float t0 = rowp[l];
            float t1 = rowp[32 + l];
            float lab = (l < 10) ? rowp[64 + l] : 0.f;
            U.r.tau[w][l] = t0; U.r.tau[w][32 + l] = t1;
            __syncwarp();

            float a1 = U.r.Be1[l];
            #pragma unroll 16
            for (int k = 0; k < 64; k++) a1 = fmaf(U.r.tau[w][k], U.r.We1[k * 32 + l], a1);
            U.r.h1[w][l] = ftanh(a1);
            __syncwarp();

            int j16 = l & 15;
            float a2 = U.r.Be2[j16];
            #pragma unroll 8
            for (int k = 0; k < 32; k++) a2 = fmaf(U.r.h1[w][k], U.r.We2[k * 16 + j16], a2);
            if (l < 16) U.r.h2[w][l] = ftanh(a2);
            __syncwarp();

            int j2 = l & 1;
            float a3 = U.r.Be3[j2];
            #pragma unroll
            for (int k = 0; k < 16; k++) a3 = fmaf(U.r.h2[w][k], U.r.We3[k * 2 + j2], a3);
            float z0 = __shfl_sync(FULLMASK, a3, 0);
            float z1 = __shfl_sync(FULLMASK, a3, 1);
            if (l == 0) g_zs[row] = make_float2(z0 * rsc, z1 * rsc);

            float ad1 = U.r.Bd1[j16] + z0 * U.r.Wd1[j16] + z1 * U.r.Wd1[16 + j16];
            if (l < 16) U.r.d1[w][l] = ftanh(ad1);
            __syncwarp();

            float ad2 = U.r.Bd2[l];
            #pragma unroll
            for (int k = 0; k < 16; k++) ad2 = fmaf(U.r.d1[w][k], U.r.Wd2[k * 32 + l], ad2);
            U.r.d2[w][l] = ftanh(ad2);
            __syncwarp();

            float o0 = U.r.Bd3[l], o1 = U.r.Bd3[32 + l];
            #pragma unroll 8
            for (int k = 0; k < 32; k++) {
                float dk = U.r.d2[w][k];
                o0 = fmaf(dk, U.r.Wd3[k * 64 + l], o0);
                o1 = fmaf(dk, U.r.Wd3[k * 64 + 32 + l], o1);
            }
            float e0 = t0 - o0, e1 = t1 - o1;
            rec_acc += e0 * e0 + e1 * e1;

            int j = (l < 10) ? l : 0;
            float dz0 = z0 - U.r.Mu[2 * j], dz1 = z1 - U.r.Mu[2 * j + 1];
            float sq = dz0 * dz0 + dz1 * dz1;
            float logit = U.r.ClsC[j] - sq * U.r.Inv2v[j];
            float lm = (l < 10) ? logit : -1e30f;
            float mx = wmax(lm);
            float ex = (l < 10) ? __expf(logit - mx) : 0.f;
            float Z = wsum(ex);
            float lsm = logit - mx - __logf(Z);
            float labsum = wsum(lab);
            float maskf = (labsum == 1.0f) ? 1.f : 0.f;
            ce_acc += (l < 10) ? (-lab * lsm * maskf) : 0.f;
            if (l == 0) den_acc += labsum;
            b_acc += (l < 10) ? U.r.Bcoef[j] * phi_sel(sq * U.r.Binv[j], K1) : 0.f;
        }

        rec_acc = wsum(rec_acc);
        ce_acc  = wsum(ce_acc);
        b_acc   = wsum(b_acc);
        den_acc = wsum(den_acc);
        if (l == 0) {
            sRed4[w][0] = (double)rec_acc; sRed4[w][1] = (double)ce_acc;
            sRed4[w][2] = (double)b_acc;   sRed4[w][3] = (double)den_acc;
        }
        __syncthreads();
        if (tid == 0) {
            double r0 = 0, r1 = 0, r2 = 0, r3 = 0;
            for (int i = 0; i < 8; i++) { r0 += sRed4[i][0]; r1 += sRed4[i][1]; r2 += sRed4[i][2]; r3 += sRed4[i][3]; }
            g_rowp[bid][0] = r0; g_rowp[bid][1] = r1;
            g_rowp[bid][2] = r2; g_rowp[bid][3] = r3;
        }
    }

    // ================= monotonic ticket barrier (replay-safe) =============
    __syncthreads();
    if (tid == 0) {
        __threadfence();
        unsigned t = atomicAdd(&g_bar, 1u);
        unsigned target = (t / NTILES + 1u) * NTILES;
        volatile unsigned* p = &g_bar;
        while (*p < target) __nanosleep(64);
    }
    __syncthreads();
    __threadfence();

    // ================= phase 2: pair tile (R10 config, 4i x 16j) ==========
    int ci = 0, rem = bid;
    for (;;) { int rl = NGRP - ci; if (rem < rl) break; rem -= rl; ci++; }
    const int cj = ci + rem;
    const bool diag = (ci == cj);

    if (tid < GRP) U.p.zi[tid] = g_zs[ci * GRP + tid];
    else U.p.zj[tid - GRP] = g_zs[cj * GRP + (tid - GRP)];
    __syncthreads();

    const int q  = l;
    const int jw = w;
    float ax0 = U.p.zi[q * 4 + 0].x, ay0 = U.p.zi[q * 4 + 0].y;
    float ax1 = U.p.zi[q * 4 + 1].x, ay1 = U.p.zi[q * 4 + 1].y;
    float ax2 = U.p.zi[q * 4 + 2].x, ay2 = U.p.zi[q * 4 + 2].y;
    float ax3 = U.p.zi[q * 4 + 3].x, ay3 = U.p.zi[q * 4 + 3].y;

    float acc0 = 0.f, acc1 = 0.f, acc2 = 0.f, acc3 = 0.f;

    #define PHI_NEAR(dxv, dyv, dst) do {                                \
        float u_ = fmaf((dxv), (dxv), fmaf((dyv), (dyv), 1.0f));        \
        float t_ = rsqa(u_);                                            \
        int ix_ = __float2int_rn(t_ * (float)TABN);                     \
        ix_ = min(ix_, TABN);                                           \
        dst = sTab[ix_];                                                \
    } while (0)

    if (!diag) {
        #pragma unroll 4
        for (int k = 0; k < 16; k++) {
            float2 b = U.p.zj[jw * 16 + k];
            float dx, dy, v;
            dx = ax0 - b.x; dy = ay0 - b.y; PHI_NEAR(dx, dy, v); acc0 += v;
            dx = ax1 - b.x; dy = ay1 - b.y; PHI_NEAR(dx, dy, v); acc1 += v;
            dx = ax2 - b.x; dy = ay2 - b.y; PHI_NEAR(dx, dy, v); acc2 += v;
            dx = ax3 - b.x; dy = ay3 - b.y; PHI_NEAR(dx, dy, v); acc3 += v;
        }
    } else {
        const int i0 = q * 4;
        #pragma unroll 4
        for (int k = 0; k < 16; k++) {
            int jl = jw * 16 + k;
            float2 b = U.p.zj[jl];
            float dx, dy, v;
            dx = ax0 - b.x; dy = ay0 - b.y; PHI_NEAR(dx, dy, v); acc0 += (jl > i0) ? v : 0.f;
            dx = ax1 - b.x; dy = ay1 - b.y; PHI_NEAR(dx, dy, v); acc1 += (jl > i0 + 1) ? v : 0.f;
            dx = ax2 - b.x; dy = ay2 - b.y; PHI_NEAR(dx, dy, v); acc2 += (jl > i0 + 2) ? v : 0.f;
            dx = ax3 - b.x; dy = ay3 - b.y; PHI_NEAR(dx, dy, v); acc3 += (jl > i0 + 3) ? v : 0.f;
        }
    }
    float acc = (acc0 + acc1) + (acc2 + acc3);
    acc = wsum(acc);
    if (l == 0) sRed[w] = (double)acc;
    __syncthreads();
    if (tid == 0) {
        double s = 0;
        for (int i = 0; i < 8; i++) s += sRed[i];
        g_pairp[bid] = s;
        __threadfence();
        unsigned v = atomicAdd(&g_done, 1u);
        sLast = ((v % NTILES) == (unsigned)(NTILES - 1));
    }
    __syncthreads();
    if (!sLast) return;
    __threadfence();

    // ================= phase 3: finalize (last-done block) ================
    double ps = 0.0;
    for (int i = tid; i < NTILES; i += 256) ps += g_pairp[i];
    double r0 = g_rowp[tid][0] + g_rowp[tid + 256][0];
    double r1 = g_rowp[tid][1] + g_rowp[tid + 256][1];
    double r2 = g_rowp[tid][2] + g_rowp[tid + 256][2];
    double r3 = g_rowp[tid][3] + g_rowp[tid + 256][3];
    double c = 0.0;
    if (tid < 100) {
        int i = tid / 10, j = tid % 10;
        float dx = means[2 * i] - means[2 * j];
        float dy = means[2 * i + 1] - means[2 * j + 1];
        float c1 = dx * dx + dy * dy;
        float vm = vars[i] + vars[j];
        float x = c1 / (2.f * vm + 4.f * gam);
        float c2 = phi_sel(x, K1);
        float c3 = probs[i] * probs[j] * rsqrtf(2.f * (float)M_PI * (vm + 2.f * gam));
        c = (double)(c3 * c2);
    }
    ps = wsumd(ps); r0 = wsumd(r0); r1 = wsumd(r1);
    r2 = wsumd(r2); r3 = wsumd(r3); c = wsumd(c);
    __shared__ double sF[8][6];
    if (l == 0) {
        sF[w][0] = ps; sF[w][1] = r0; sF[w][2] = r1;
        sF[w][3] = r2; sF[w][4] = r3; sF[w][5] = c;
    }
    __syncthreads();
    if (tid == 0) {
        double Ps = 0, Rec = 0, Ce = 0, Bt = 0, Den = 0, Ct = 0;
        for (int i = 0; i < 8; i++) {
            Ps += sF[i][0]; Rec += sF[i][1]; Ce += sF[i][2];
            Bt += sF[i][3]; Den += sF[i][4]; Ct += sF[i][5];
        }
        double m = (double)MROWS;
        double A = (2.0 * Ps + m * phi0) * scaleA;
        double rec = Rec / (m * 64.0);
        if (Den == 0.0) Den = 1.0;
        double cls = Ce / Den;
        double cw = A - Bt + Ct;
        out[0] = (float)(rec + 8.0 + log(cw) + 2.0 * cls);
    }
}

extern "C" void kernel_launch(void* const* d_in, const int* in_sizes, int n_in,
                              void* d_out, int out_size) {
    const float* bd   = (const float*)d_in[0];
    const float* We1  = (const float*)d_in[1];
    const float* be1  = (const float*)d_in[2];
    const float* We2  = (const float*)d_in[3];
    const float* be2  = (const float*)d_in[4];
    const float* We3  = (const float*)d_in[5];
    const float* be3  = (const float*)d_in[6];
    const float* Wd1  = (const float*)d_in[7];
    const float* bd1  = (const float*)d_in[8];
    const float* Wd2  = (const float*)d_in[9];
    const float* bd2  = (const float*)d_in[10];
    const float* Wd3  = (const float*)d_in[11];
    const float* bd3  = (const float*)d_in[12];
    const float* means = (const float*)d_in[13];
    const float* vars  = (const float*)d_in[14];
    const float* probs = (const float*)d_in[15];
    float* out = (float*)d_out;

    const double m = (double)MROWS;
    const double gamma = pow(4.0 / (3.0 * m), 0.2);
    const double pf75 = exp(-3.75) * (1.0 + 3.5156229 + 3.0899424 + 1.2067492 +
                                      0.2659732 + 0.0360768 + 0.0045813);
    const double pg75 = sqrt(2.0 / 7.5) * (0.39894228 + 0.01328592 + 0.00225319 -
                                           0.00157565 + 0.0091628 - 0.02057706 +
                                           0.02635537 - 0.01647633 + 0.00392377);
    const double K1 = pg75 - pf75;
    const double phi0 = 1.0 + K1;
    const double scaleA = 1.0 / (m * m * sqrt(2.0 * M_PI * 2.0 * gamma));
    const float rsc = (float)(1.0 / sqrt(4.0 * gamma));

    segma_one<<<NTILES, 256>>>(bd, We1, be1, We2, be2, We3, be3,
                               Wd1, bd1, Wd2, bd2, Wd3, bd3,
                               means, vars, probs, out,
                               (float)K1, rsc, (float)gamma, phi0, scaleA);
}

// round 15
// speedup vs baseline: 1.3161x; 1.3161x over previous
#include <cuda_runtime.h>
#include <math.h>

#ifndef M_PI
#define M_PI 3.14159265358979323846
#endif

#define MROWS 4096
#define ROWSTRIDE 74
#define GRP 128
#define NGRP 32
#define NTILES 528          // 32*33/2
#define NROWBLK 512
#define TABN 1024           // index = round(t*TABN); +2 guard entries
#define FULLMASK 0xffffffffu

__device__ float2 g_zs[MROWS];
__device__ float g_tabN[TABN + 3];      // phi LUT (nearest) over t = rsqrt(1+s)
__device__ double g_pairp[NTILES];
__device__ double g_rowp[NROWBLK][4];   // rec, ce, b, den
__device__ unsigned g_done;

// ---- small branch: poly in s^2, coeffs folded with (1/56.25)^k ----
#define P56 56.25
#define BC0 ((float)(3.5156229 / P56))
#define BC1 ((float)(3.0899424 / (P56 * P56)))
#define BC2 ((float)(1.2067492 / (P56 * P56 * P56)))
#define BC3 ((float)(0.2659732 / (P56 * P56 * P56 * P56)))
#define BC4 ((float)(0.0360768 / (P56 * P56 * P56 * P56 * P56)))
#define BC5 ((float)(0.0045813 / (P56 * P56 * P56 * P56 * P56 * P56)))
// ---- large branch: coeffs folded with sqrt(2)*7.5^k, poly in 1/s ----
#define SQ2 1.4142135623730951
#define QD0 ((float)(0.39894228 * SQ2))
#define QD1 ((float)(0.01328592 * SQ2 * 7.5))
#define QD2 ((float)(0.00225319 * SQ2 * 56.25))
#define QD3 ((float)(-0.00157565 * SQ2 * 421.875))
#define QD4 ((float)(0.0091628 * SQ2 * 3164.0625))
#define QD5 ((float)(-0.02057706 * SQ2 * 23730.46875))
#define QD6 ((float)(0.02635537 * SQ2 * 177978.515625))
#define QD7 ((float)(-0.01647633 * SQ2 * 1334838.8671875))
#define QD8 ((float)(0.00392377 * SQ2 * 10011291.50390625))

#define MAGICF 12582912.0f          // 1.5 * 2^23
#define MAGICI 0x4B400000

__device__ __forceinline__ float rsqa(float x) {
    float r; asm("rsqrt.approx.f32 %0,%1;" : "=f"(r) : "f"(x)); return r;
}

// exact reference phi (rows / finalize / table build)
__device__ __forceinline__ float phi_sel(float s, float K1) {
    float s2 = s * s;
    float p = fmaf(s2, BC5, BC4);
    p = fmaf(s2, p, BC3);
    p = fmaf(s2, p, BC2);
    p = fmaf(s2, p, BC1);
    p = fmaf(s2, p, BC0);
    p = fmaf(s2, p, 1.0f);
    float e  = __expf(-0.5f * s);
    float sv = fmaf(p, e, K1);
    float r  = rsqrtf(s);
    float iv = r * r;
    float q = fmaf(iv, QD8, QD7);
    q = fmaf(iv, q, QD6);
    q = fmaf(iv, q, QD5);
    q = fmaf(iv, q, QD4);
    q = fmaf(iv, q, QD3);
    q = fmaf(iv, q, QD2);
    q = fmaf(iv, q, QD1);
    q = fmaf(iv, q, QD0);
    float bv = r * q;
    return (s <= 7.5f) ? sv : bv;
}

__device__ __forceinline__ float phi_of_t(float t, float K1) {
    if (t <= 0.f) return 0.f;
    double td = (double)t;
    double sd = 1.0 / (td * td) - 1.0;
    if (sd < 0.0) sd = 0.0;
    return phi_sel((float)sd, K1);
}

__device__ __forceinline__ float ftanh(float x) {
    float e = __expf(2.f * x);
    return 1.f - __fdividef(2.f, e + 1.f);
}
__device__ __forceinline__ float wsum(float v) {
    #pragma unroll
    for (int o = 16; o; o >>= 1) v += __shfl_xor_sync(FULLMASK, v, o);
    return v;
}
__device__ __forceinline__ double wsumd(double v) {
    #pragma unroll
    for (int o = 16; o; o >>= 1) v += __shfl_xor_sync(FULLMASK, v, o);
    return v;
}
__device__ __forceinline__ float wmax(float v) {
    #pragma unroll
    for (int o = 16; o; o >>= 1) v = fmaxf(v, __shfl_xor_sync(FULLMASK, v, o));
    return v;
}

// ---------------- rows kernel: 512 blocks, 1 row/warp; block 0 builds LUT ----
__global__ void __launch_bounds__(256) k_rows(
    const float* __restrict__ bd,
    const float* __restrict__ We1, const float* __restrict__ be1,
    const float* __restrict__ We2, const float* __restrict__ be2,
    const float* __restrict__ We3, const float* __restrict__ be3,
    const float* __restrict__ Wd1, const float* __restrict__ bd1,
    const float* __restrict__ Wd2, const float* __restrict__ bd2,
    const float* __restrict__ Wd3, const float* __restrict__ bd3,
    const float* __restrict__ means, const float* __restrict__ vars,
    const float* __restrict__ probs,
    float K1, float rsc, float gam)
{
    __shared__ float sWe1[2048], sWe2[512], sWe3[32], sWd1[32], sWd2[512], sWd3[2048];
    __shared__ float sBe1[32], sBe2[16], sBe3[2], sBd1[16], sBd2[32], sBd3[64];
    __shared__ float sClsC[10], sInv2v[10], sBcoef[10], sBinv[10], sMu[20];
    __shared__ float stau[8][64], sh1[8][32], sh2[8][16], sd1[8][16], sd2[8][32];
    __shared__ double sRed4[8][4];

    const int tid = threadIdx.x;
    const int w   = tid >> 5;
    const int l   = tid & 31;

    if (blockIdx.x == 0) {
        if (tid == 0) g_done = 0;
        for (int e = tid; e < TABN + 3; e += 256) {
            int ec = (e > TABN) ? TABN : e;      // guard entries replicate t=1
            float t = (float)ec / (float)TABN;
            g_tabN[e] = phi_of_t(t, K1);
        }
    }

    for (int i = tid; i < 2048; i += 256) { sWe1[i] = We1[i]; sWd3[i] = Wd3[i]; }
    for (int i = tid; i < 512;  i += 256) { sWe2[i] = We2[i]; sWd2[i] = Wd2[i]; }
    if (tid < 32) { sWe3[tid] = We3[tid]; sWd1[tid] = Wd1[tid]; sBe1[tid] = be1[tid]; sBd2[tid] = bd2[tid]; }
    if (tid < 16) { sBe2[tid] = be2[tid]; sBd1[tid] = bd1[tid]; }
    if (tid < 2)  { sBe3[tid] = be3[tid]; }
    if (tid < 64) { sBd3[tid] = bd3[tid]; }
    if (tid < 20) sMu[tid] = means[tid];
    if (tid < 10) {
        float v = vars[tid], p = probs[tid];
        sClsC[tid]  = logf(p) - logf(2.f * (float)M_PI * v);
        sInv2v[tid] = 0.5f / v;
        float vp2g = v + 2.f * gam;
        sBcoef[tid] = 2.f * p / ((float)MROWS * sqrtf(2.f * (float)M_PI * vp2g));
        sBinv[tid]  = 0.5f / vp2g;
    }
    __syncthreads();

    float rec_acc = 0.f, ce_acc = 0.f, b_acc = 0.f, den_acc = 0.f;
    {
        int row = blockIdx.x * 8 + w;
        const float* rowp = bd + row * ROWSTRIDE;
        float t0 = rowp[l];
        float t1 = rowp[32 + l];
        float lab = (l < 10) ? rowp[64 + l] : 0.f;
        stau[w][l] = t0; stau[w][32 + l] = t1;
        __syncwarp();

        float a1 = sBe1[l];
        #pragma unroll 16
        for (int k = 0; k < 64; k++) a1 = fmaf(stau[w][k], sWe1[k * 32 + l], a1);
        sh1[w][l] = ftanh(a1);
        __syncwarp();

        int j16 = l & 15;
        float a2 = sBe2[j16];
        #pragma unroll 8
        for (int k = 0; k < 32; k++) a2 = fmaf(sh1[w][k], sWe2[k * 16 + j16], a2);
        if (l < 16) sh2[w][l] = ftanh(a2);
        __syncwarp();

        int j2 = l & 1;
        float a3 = sBe3[j2];
        #pragma unroll
        for (int k = 0; k < 16; k++) a3 = fmaf(sh2[w][k], sWe3[k * 2 + j2], a3);
        float z0 = __shfl_sync(FULLMASK, a3, 0);
        float z1 = __shfl_sync(FULLMASK, a3, 1);
        if (l == 0) g_zs[row] = make_float2(z0 * rsc, z1 * rsc);

        float ad1 = sBd1[j16] + z0 * sWd1[j16] + z1 * sWd1[16 + j16];
        if (l < 16) sd1[w][l] = ftanh(ad1);
        __syncwarp();

        float ad2 = sBd2[l];
        #pragma unroll
        for (int k = 0; k < 16; k++) ad2 = fmaf(sd1[w][k], sWd2[k * 32 + l], ad2);
        sd2[w][l] = ftanh(ad2);
        __syncwarp();

        float o0 = sBd3[l], o1 = sBd3[32 + l];
        #pragma unroll 8
        for (int k = 0; k < 32; k++) {
            float dk = sd2[w][k];
            o0 = fmaf(dk, sWd3[k * 64 + l], o0);
            o1 = fmaf(dk, sWd3[k * 64 + 32 + l], o1);
        }
        float e0 = t0 - o0, e1 = t1 - o1;
        rec_acc += e0 * e0 + e1 * e1;

        int j = (l < 10) ? l : 0;
        float dz0 = z0 - sMu[2 * j], dz1 = z1 - sMu[2 * j + 1];
        float sq = dz0 * dz0 + dz1 * dz1;
        float logit = sClsC[j] - sq * sInv2v[j];
        float lm = (l < 10) ? logit : -1e30f;
        float mx = wmax(lm);
        float ex = (l < 10) ? __expf(logit - mx) : 0.f;
        float Z = wsum(ex);
        float lsm = logit - mx - __logf(Z);
        float labsum = wsum(lab);
        float maskf = (labsum == 1.0f) ? 1.f : 0.f;
        ce_acc += (l < 10) ? (-lab * lsm * maskf) : 0.f;
        if (l == 0) den_acc += labsum;
        b_acc += (l < 10) ? sBcoef[j] * phi_sel(sq * sBinv[j], K1) : 0.f;
    }

    rec_acc = wsum(rec_acc);
    ce_acc  = wsum(ce_acc);
    b_acc   = wsum(b_acc);
    den_acc = wsum(den_acc);
    if (l == 0) {
        sRed4[w][0] = (double)rec_acc; sRed4[w][1] = (double)ce_acc;
        sRed4[w][2] = (double)b_acc;   sRed4[w][3] = (double)den_acc;
    }
    __syncthreads();
    if (tid == 0) {
        double r0 = 0, r1 = 0, r2 = 0, r3 = 0;
        for (int i = 0; i < 8; i++) { r0 += sRed4[i][0]; r1 += sRed4[i][1]; r2 += sRed4[i][2]; r3 += sRed4[i][3]; }
        g_rowp[blockIdx.x][0] = r0; g_rowp[blockIdx.x][1] = r1;
        g_rowp[blockIdx.x][2] = r2; g_rowp[blockIdx.x][3] = r3;
    }
}

// ---- pairs kernel: 256 thr, magic-round LUT phi, 128x128, 4i x 16j --------
__global__ void __launch_bounds__(256) k_pairs(
    const float* __restrict__ means, const float* __restrict__ vars,
    const float* __restrict__ probs, float* __restrict__ out,
    float K1, float gam, double phi0, double scaleA)
{
    __shared__ float sTab[TABN + 3];
    __shared__ float2 zi[GRP], zj[GRP];
    __shared__ double sRed[8];
    __shared__ bool sLast;

    const int tid = threadIdx.x;
    const int w   = tid >> 5;
    const int l   = tid & 31;
    const int bid = blockIdx.x;

    int ci = 0, rem = bid;
    for (;;) { int rl = NGRP - ci; if (rem < rl) break; rem -= rl; ci++; }
    const int cj = ci + rem;
    const bool diag = (ci == cj);

    // stage LUT + z tiles
    for (int i = tid; i < TABN + 3; i += 256) sTab[i] = g_tabN[i];
    if (tid < GRP) zi[tid] = g_zs[ci * GRP + tid];
    else zj[tid - GRP] = g_zs[cj * GRP + (tid - GRP)];
    __syncthreads();

    const int q  = l;
    const int jw = w;
    float ax0 = zi[q * 4 + 0].x, ay0 = zi[q * 4 + 0].y;
    float ax1 = zi[q * 4 + 1].x, ay1 = zi[q * 4 + 1].y;
    float ax2 = zi[q * 4 + 2].x, ay2 = zi[q * 4 + 2].y;
    float ax3 = zi[q * 4 + 3].x, ay3 = zi[q * 4 + 3].y;

    float acc0 = 0.f, acc1 = 0.f, acc2 = 0.f, acc3 = 0.f;

    // magic-number rounding: no F2I, no clamp (guard entries absorb t ~ 1+eps)
    #define PHI_NEAR(dxv, dyv, dst) do {                                \
        float u_ = fmaf((dxv), (dxv), fmaf((dyv), (dyv), 1.0f));        \
        float t_ = rsqa(u_);                                            \
        float fi_ = fmaf(t_, (float)TABN, MAGICF);                      \
        int ix_ = __float_as_int(fi_) - MAGICI;                         \
        dst = sTab[ix_];                                                \
    } while (0)

    if (!diag) {
        #pragma unroll
        for (int k = 0; k < 16; k++) {
            float2 b = zj[jw * 16 + k];
            float dx, dy, v;
            dx = ax0 - b.x; dy = ay0 - b.y; PHI_NEAR(dx, dy, v); acc0 += v;
            dx = ax1 - b.x; dy = ay1 - b.y; PHI_NEAR(dx, dy, v); acc1 += v;
            dx = ax2 - b.x; dy = ay2 - b.y; PHI_NEAR(dx, dy, v); acc2 += v;
            dx = ax3 - b.x; dy = ay3 - b.y; PHI_NEAR(dx, dy, v); acc3 += v;
        }
    } else {
        const int i0 = q * 4;
        #pragma unroll
        for (int k = 0; k < 16; k++) {
            int jl = jw * 16 + k;
            float2 b = zj[jl];
            float dx, dy, v;
            dx = ax0 - b.x; dy = ay0 - b.y; PHI_NEAR(dx, dy, v); acc0 += (jl > i0) ? v : 0.f;
            dx = ax1 - b.x; dy = ay1 - b.y; PHI_NEAR(dx, dy, v); acc1 += (jl > i0 + 1) ? v : 0.f;
            dx = ax2 - b.x; dy = ay2 - b.y; PHI_NEAR(dx, dy, v); acc2 += (jl > i0 + 2) ? v : 0.f;
            dx = ax3 - b.x; dy = ay3 - b.y; PHI_NEAR(dx, dy, v); acc3 += (jl > i0 + 3) ? v : 0.f;
        }
    }
    float acc = (acc0 + acc1) + (acc2 + acc3);
    acc = wsum(acc);
    if (l == 0) sRed[w] = (double)acc;
    __syncthreads();
    if (tid == 0) {
        double s = 0;
        for (int i = 0; i < 8; i++) s += sRed[i];
        g_pairp[bid] = s;
        __threadfence();
        unsigned v = atomicAdd(&g_done, 1u);
        sLast = (v == (unsigned)(NTILES - 1));
    }
    __syncthreads();
    if (!sLast) return;
    __threadfence();

    // ---- fused finalize (last block only) ----
    double ps = 0.0;
    for (int i = tid; i < NTILES; i += 256) ps += g_pairp[i];
    double r0 = g_rowp[tid][0] + g_rowp[tid + 256][0];
    double r1 = g_rowp[tid][1] + g_rowp[tid + 256][1];
    double r2 = g_rowp[tid][2] + g_rowp[tid + 256][2];
    double r3 = g_rowp[tid][3] + g_rowp[tid + 256][3];
    double c = 0.0;
    if (tid < 100) {
        int i = tid / 10, j = tid % 10;
        float dx = means[2 * i] - means[2 * j];
        float dy = means[2 * i + 1] - means[2 * j + 1];
        float c1 = dx * dx + dy * dy;
        float vm = vars[i] + vars[j];
        float x = c1 / (2.f * vm + 4.f * gam);
        float c2 = phi_sel(x, K1);
        float c3 = probs[i] * probs[j] * rsqrtf(2.f * (float)M_PI * (vm + 2.f * gam));
        c = (double)(c3 * c2);
    }
    ps = wsumd(ps); r0 = wsumd(r0); r1 = wsumd(r1);
    r2 = wsumd(r2); r3 = wsumd(r3); c = wsumd(c);
    __shared__ double sF[8][6];
    if (l == 0) {
        sF[w][0] = ps; sF[w][1] = r0; sF[w][2] = r1;
        sF[w][3] = r2; sF[w][4] = r3; sF[w][5] = c;
    }
    __syncthreads();
    if (tid == 0) {
        double Ps = 0, Rec = 0, Ce = 0, Bt = 0, Den = 0, Ct = 0;
        for (int i = 0; i < 8; i++) {
            Ps += sF[i][0]; Rec += sF[i][1]; Ce += sF[i][2];
            Bt += sF[i][3]; Den += sF[i][4]; Ct += sF[i][5];
        }
        double m = (double)MROWS;
        double A = (2.0 * Ps + m * phi0) * scaleA;
        double rec = Rec / (m * 64.0);
        if (Den == 0.0) Den = 1.0;
        double cls = Ce / Den;
        double cw = A - Bt + Ct;
        out[0] = (float)(rec + 8.0 + log(cw) + 2.0 * cls);
    }
}

extern "C" void kernel_launch(void* const* d_in, const int* in_sizes, int n_in,
                              void* d_out, int out_size) {
    const float* bd   = (const float*)d_in[0];
    const float* We1  = (const float*)d_in[1];
    const float* be1  = (const float*)d_in[2];
    const float* We2  = (const float*)d_in[3];
    const float* be2  = (const float*)d_in[4];
    const float* We3  = (const float*)d_in[5];
    const float* be3  = (const float*)d_in[6];
    const float* Wd1  = (const float*)d_in[7];
    const float* bd1  = (const float*)d_in[8];
    const float* Wd2  = (const float*)d_in[9];
    const float* bd2  = (const float*)d_in[10];
    const float* Wd3  = (const float*)d_in[11];
    const float* bd3  = (const float*)d_in[12];
    const float* means = (const float*)d_in[13];
    const float* vars  = (const float*)d_in[14];
    const float* probs = (const float*)d_in[15];
    float* out = (float*)d_out;

    const double m = (double)MROWS;
    const double gamma = pow(4.0 / (3.0 * m), 0.2);
    const double pf75 = exp(-3.75) * (1.0 + 3.5156229 + 3.0899424 + 1.2067492 +
                                      0.2659732 + 0.0360768 + 0.0045813);
    const double pg75 = sqrt(2.0 / 7.5) * (0.39894228 + 0.01328592 + 0.00225319 -
                                           0.00157565 + 0.0091628 - 0.02057706 +
                                           0.02635537 - 0.01647633 + 0.00392377);
    const double K1 = pg75 - pf75;
    const double phi0 = 1.0 + K1;
    const double scaleA = 1.0 / (m * m * sqrt(2.0 * M_PI * 2.0 * gamma));
    const float rsc = (float)(1.0 / sqrt(4.0 * gamma));

    k_rows<<<NROWBLK, 256>>>(bd, We1, be1, We2, be2, We3, be3,
                             Wd1, bd1, Wd2, bd2, Wd3, bd3,
                             means, vars, probs, (float)K1, rsc, (float)gamma);
    k_pairs<<<NTILES, 256>>>(means, vars, probs, out,
                             (float)K1, (float)gamma, phi0, scaleA);
}

// round 16
// speedup vs baseline: 1.4405x; 1.0945x over previous
#include <cuda_runtime.h>
#include <math.h>

#ifndef M_PI
#define M_PI 3.14159265358979323846
#endif

#define MROWS 4096
#define ROWSTRIDE 74
#define GRP 128
#define NGRP 32
#define NTILES 528          // 32*33/2
#define NROWBLK 512
#define TABN 1024
#define TABSZ 1028          // TABN+4: guards + float4 pad
#define FULLMASK 0xffffffffu

__device__ __align__(16) float2 g_zs[MROWS];
__device__ __align__(16) float g_tabN[TABSZ];
__device__ double g_pairp[NTILES];
__device__ double g_rowp[NROWBLK][4];   // rec, ce, b, den
__device__ unsigned g_done;

// ---- small branch: poly in s^2, coeffs folded with (1/56.25)^k ----
#define P56 56.25
#define BC0 ((float)(3.5156229 / P56))
#define BC1 ((float)(3.0899424 / (P56 * P56)))
#define BC2 ((float)(1.2067492 / (P56 * P56 * P56)))
#define BC3 ((float)(0.2659732 / (P56 * P56 * P56 * P56)))
#define BC4 ((float)(0.0360768 / (P56 * P56 * P56 * P56 * P56)))
#define BC5 ((float)(0.0045813 / (P56 * P56 * P56 * P56 * P56 * P56)))
// ---- large branch: coeffs folded with sqrt(2)*7.5^k, poly in 1/s ----
#define SQ2 1.4142135623730951
#define QD0 ((float)(0.39894228 * SQ2))
#define QD1 ((float)(0.01328592 * SQ2 * 7.5))
#define QD2 ((float)(0.00225319 * SQ2 * 56.25))
#define QD3 ((float)(-0.00157565 * SQ2 * 421.875))
#define QD4 ((float)(0.0091628 * SQ2 * 3164.0625))
#define QD5 ((float)(-0.02057706 * SQ2 * 23730.46875))
#define QD6 ((float)(0.02635537 * SQ2 * 177978.515625))
#define QD7 ((float)(-0.01647633 * SQ2 * 1334838.8671875))
#define QD8 ((float)(0.00392377 * SQ2 * 10011291.50390625))

#define MAGICF 12582912.0f          // 1.5 * 2^23
#define MAGICI 0x4B400000

__device__ __forceinline__ float rsqa(float x) {
    float r; asm("rsqrt.approx.f32 %0,%1;" : "=f"(r) : "f"(x)); return r;
}

// exact reference phi (rows / finalize / table build)
__device__ __forceinline__ float phi_sel(float s, float K1) {
    float s2 = s * s;
    float p = fmaf(s2, BC5, BC4);
    p = fmaf(s2, p, BC3);
    p = fmaf(s2, p, BC2);
    p = fmaf(s2, p, BC1);
    p = fmaf(s2, p, BC0);
    p = fmaf(s2, p, 1.0f);
    float e  = __expf(-0.5f * s);
    float sv = fmaf(p, e, K1);
    float r  = rsqrtf(s);
    float iv = r * r;
    float q = fmaf(iv, QD8, QD7);
    q = fmaf(iv, q, QD6);
    q = fmaf(iv, q, QD5);
    q = fmaf(iv, q, QD4);
    q = fmaf(iv, q, QD3);
    q = fmaf(iv, q, QD2);
    q = fmaf(iv, q, QD1);
    q = fmaf(iv, q, QD0);
    float bv = r * q;
    return (s <= 7.5f) ? sv : bv;
}

__device__ __forceinline__ float phi_of_t(float t, float K1) {
    if (t <= 0.f) return 0.f;
    double td = (double)t;
    double sd = 1.0 / (td * td) - 1.0;
    if (sd < 0.0) sd = 0.0;
    return phi_sel((float)sd, K1);
}

__device__ __forceinline__ float ftanh(float x) {
    float e = __expf(2.f * x);
    return 1.f - __fdividef(2.f, e + 1.f);
}
__device__ __forceinline__ float wsum(float v) {
    #pragma unroll
    for (int o = 16; o; o >>= 1) v += __shfl_xor_sync(FULLMASK, v, o);
    return v;
}
__device__ __forceinline__ double wsumd(double v) {
    #pragma unroll
    for (int o = 16; o; o >>= 1) v += __shfl_xor_sync(FULLMASK, v, o);
    return v;
}
__device__ __forceinline__ float wmax(float v) {
    #pragma unroll
    for (int o = 16; o; o >>= 1) v = fmaxf(v, __shfl_xor_sync(FULLMASK, v, o));
    return v;
}

// ---------------- rows kernel: 512 blocks, 1 row/warp; block 0 builds LUT ----
__global__ void __launch_bounds__(256) k_rows(
    const float* __restrict__ bd,
    const float* __restrict__ We1, const float* __restrict__ be1,
    const float* __restrict__ We2, const float* __restrict__ be2,
    const float* __restrict__ We3, const float* __restrict__ be3,
    const float* __restrict__ Wd1, const float* __restrict__ bd1,
    const float* __restrict__ Wd2, const float* __restrict__ bd2,
    const float* __restrict__ Wd3, const float* __restrict__ bd3,
    const float* __restrict__ means, const float* __restrict__ vars,
    const float* __restrict__ probs,
    float K1, float rsc, float gam)
{
    __shared__ __align__(16) float sWe1[2048], sWd3[2048], sWe2[512], sWd2[512];
    __shared__ float sWe3[32], sWd1[32];
    __shared__ float sBe1[32], sBe2[16], sBe3[2], sBd1[16], sBd2[32], sBd3[64];
    __shared__ float sClsC[10], sInv2v[10], sBcoef[10], sBinv[10], sMu[20];
    __shared__ float stau[8][64], sh1[8][32], sh2[8][16], sd1[8][16], sd2[8][32];
    __shared__ double sRed4[8][4];

    const int tid = threadIdx.x;
    const int w   = tid >> 5;
    const int l   = tid & 31;

    if (blockIdx.x == 0) {
        if (tid == 0) g_done = 0;
        for (int e = tid; e < TABSZ; e += 256) {
            int ec = (e > TABN) ? TABN : e;      // guard entries replicate t=1
            float t = (float)ec / (float)TABN;
            g_tabN[e] = phi_of_t(t, K1);
        }
    }

    // float4 weight staging
    {
        float4* d1v = (float4*)sWe1; const float4* s1v = (const float4*)We1;
        float4* d2v = (float4*)sWd3; const float4* s2v = (const float4*)Wd3;
        #pragma unroll
        for (int r = 0; r < 2; r++) {
            d1v[tid + r * 256] = s1v[tid + r * 256];
            d2v[tid + r * 256] = s2v[tid + r * 256];
        }
        if (tid < 128) {
            ((float4*)sWe2)[tid] = ((const float4*)We2)[tid];
            ((float4*)sWd2)[tid] = ((const float4*)Wd2)[tid];
        }
    }
    if (tid < 32) { sWe3[tid] = We3[tid]; sWd1[tid] = Wd1[tid]; sBe1[tid] = be1[tid]; sBd2[tid] = bd2[tid]; }
    if (tid < 16) { sBe2[tid] = be2[tid]; sBd1[tid] = bd1[tid]; }
    if (tid < 2)  { sBe3[tid] = be3[tid]; }
    if (tid < 64) { sBd3[tid] = bd3[tid]; }
    if (tid < 20) sMu[tid] = means[tid];
    if (tid < 10) {
        float v = vars[tid], p = probs[tid];
        sClsC[tid]  = logf(p) - logf(2.f * (float)M_PI * v);
        sInv2v[tid] = 0.5f / v;
        float vp2g = v + 2.f * gam;
        sBcoef[tid] = 2.f * p / ((float)MROWS * sqrtf(2.f * (float)M_PI * vp2g));
        sBinv[tid]  = 0.5f / vp2g;
    }
    __syncthreads();

    float rec_acc = 0.f, ce_acc = 0.f, b_acc = 0.f, den_acc = 0.f;
    {
        int row = blockIdx.x * 8 + w;
        const float* rowp = bd + row * ROWSTRIDE;
        float t0 = rowp[l];
        float t1 = rowp[32 + l];
        float lab = (l < 10) ? rowp[64 + l] : 0.f;
        stau[w][l] = t0; stau[w][32 + l] = t1;
        __syncwarp();

        float a1 = sBe1[l];
        #pragma unroll 16
        for (int k = 0; k < 64; k++) a1 = fmaf(stau[w][k], sWe1[k * 32 + l], a1);
        sh1[w][l] = ftanh(a1);
        __syncwarp();

        int j16 = l & 15;
        float a2 = sBe2[j16];
        #pragma unroll 8
        for (int k = 0; k < 32; k++) a2 = fmaf(sh1[w][k], sWe2[k * 16 + j16], a2);
        if (l < 16) sh2[w][l] = ftanh(a2);
        __syncwarp();

        int j2 = l & 1;
        float a3 = sBe3[j2];
        #pragma unroll
        for (int k = 0; k < 16; k++) a3 = fmaf(sh2[w][k], sWe3[k * 2 + j2], a3);
        float z0 = __shfl_sync(FULLMASK, a3, 0);
        float z1 = __shfl_sync(FULLMASK, a3, 1);
        if (l == 0) g_zs[row] = make_float2(z0 * rsc, z1 * rsc);

        float ad1 = sBd1[j16] + z0 * sWd1[j16] + z1 * sWd1[16 + j16];
        if (l < 16) sd1[w][l] = ftanh(ad1);
        __syncwarp();

        float ad2 = sBd2[l];
        #pragma unroll
        for (int k = 0; k < 16; k++) ad2 = fmaf(sd1[w][k], sWd2[k * 32 + l], ad2);
        sd2[w][l] = ftanh(ad2);
        __syncwarp();

        float o0 = sBd3[l], o1 = sBd3[32 + l];
        #pragma unroll 8
        for (int k = 0; k < 32; k++) {
            float dk = sd2[w][k];
            o0 = fmaf(dk, sWd3[k * 64 + l], o0);
            o1 = fmaf(dk, sWd3[k * 64 + 32 + l], o1);
        }
        float e0 = t0 - o0, e1 = t1 - o1;
        rec_acc += e0 * e0 + e1 * e1;

        int j = (l < 10) ? l : 0;
        float dz0 = z0 - sMu[2 * j], dz1 = z1 - sMu[2 * j + 1];
        float sq = dz0 * dz0 + dz1 * dz1;
        float logit = sClsC[j] - sq * sInv2v[j];
        float lm = (l < 10) ? logit : -1e30f;
        float mx = wmax(lm);
        float ex = (l < 10) ? __expf(logit - mx) : 0.f;
        float Z = wsum(ex);
        float lsm = logit - mx - __logf(Z);
        float labsum = wsum(lab);
        float maskf = (labsum == 1.0f) ? 1.f : 0.f;
        ce_acc += (l < 10) ? (-lab * lsm * maskf) : 0.f;
        if (l == 0) den_acc += labsum;
        b_acc += (l < 10) ? sBcoef[j] * phi_sel(sq * sBinv[j], K1) : 0.f;
    }

    rec_acc = wsum(rec_acc);
    ce_acc  = wsum(ce_acc);
    b_acc   = wsum(b_acc);
    den_acc = wsum(den_acc);
    if (l == 0) {
        sRed4[w][0] = (double)rec_acc; sRed4[w][1] = (double)ce_acc;
        sRed4[w][2] = (double)b_acc;   sRed4[w][3] = (double)den_acc;
    }
    __syncthreads();
    if (tid == 0) {
        double r0 = 0, r1 = 0, r2 = 0, r3 = 0;
        for (int i = 0; i < 8; i++) { r0 += sRed4[i][0]; r1 += sRed4[i][1]; r2 += sRed4[i][2]; r3 += sRed4[i][3]; }
        g_rowp[blockIdx.x][0] = r0; g_rowp[blockIdx.x][1] = r1;
        g_rowp[blockIdx.x][2] = r2; g_rowp[blockIdx.x][3] = r3;
    }
}

// ---- pairs kernel: 256 thr, magic-round LUT, 128x128, 8 LDS in flight -----
__global__ void __launch_bounds__(256) k_pairs(
    const float* __restrict__ means, const float* __restrict__ vars,
    const float* __restrict__ probs, float* __restrict__ out,
    float K1, float gam, double phi0, double scaleA)
{
    __shared__ __align__(16) float sTab[TABSZ];
    __shared__ __align__(16) float2 zi[GRP], zj[GRP];
    __shared__ double sRed[8];
    __shared__ bool sLast;

    const int tid = threadIdx.x;
    const int w   = tid >> 5;
    const int l   = tid & 31;
    const int bid = blockIdx.x;

    int ci = 0, rem = bid;
    for (;;) { int rl = NGRP - ci; if (rem < rl) break; rem -= rl; ci++; }
    const int cj = ci + rem;
    const bool diag = (ci == cj);

    // float4 staging: LUT (257 vec4) + z tiles (64 vec4 each)
    {
        float4* tv = (float4*)sTab; const float4* gv = (const float4*)g_tabN;
        if (tid < 257) tv[tid] = gv[tid];
        const float4* zsv = (const float4*)g_zs;
        if (tid >= 64 && tid < 128) ((float4*)zi)[tid - 64] = zsv[ci * 64 + (tid - 64)];
        else if (tid >= 128 && tid < 192) ((float4*)zj)[tid - 128] = zsv[cj * 64 + (tid - 128)];
    }
    __syncthreads();

    const int q  = l;
    const int jw = w;
    float ax0 = zi[q * 4 + 0].x, ay0 = zi[q * 4 + 0].y;
    float ax1 = zi[q * 4 + 1].x, ay1 = zi[q * 4 + 1].y;
    float ax2 = zi[q * 4 + 2].x, ay2 = zi[q * 4 + 2].y;
    float ax3 = zi[q * 4 + 3].x, ay3 = zi[q * 4 + 3].y;

    float acc0 = 0.f, acc1 = 0.f, acc2 = 0.f, acc3 = 0.f;

    #define PHI_NEAR(dxv, dyv, dst) do {                                \
        float u_ = fmaf((dxv), (dxv), fmaf((dyv), (dyv), 1.0f));        \
        float t_ = rsqa(u_);                                            \
        float fi_ = fmaf(t_, (float)TABN, MAGICF);                      \
        int ix_ = __float_as_int(fi_) - MAGICI;                         \
        dst = sTab[ix_];                                                \
    } while (0)

    if (!diag) {
        #pragma unroll
        for (int k = 0; k < 8; k++) {
            float2 bA = zj[jw * 16 + k];
            float2 bB = zj[jw * 16 + k + 8];
            float dx, dy, vA0, vA1, vA2, vA3, vB0, vB1, vB2, vB3;
            dx = ax0 - bA.x; dy = ay0 - bA.y; PHI_NEAR(dx, dy, vA0);
            dx = ax1 - bA.x; dy = ay1 - bA.y; PHI_NEAR(dx, dy, vA1);
            dx = ax2 - bA.x; dy = ay2 - bA.y; PHI_NEAR(dx, dy, vA2);
            dx = ax3 - bA.x; dy = ay3 - bA.y; PHI_NEAR(dx, dy, vA3);
            dx = ax0 - bB.x; dy = ay0 - bB.y; PHI_NEAR(dx, dy, vB0);
            dx = ax1 - bB.x; dy = ay1 - bB.y; PHI_NEAR(dx, dy, vB1);
            dx = ax2 - bB.x; dy = ay2 - bB.y; PHI_NEAR(dx, dy, vB2);
            dx = ax3 - bB.x; dy = ay3 - bB.y; PHI_NEAR(dx, dy, vB3);
            acc0 += vA0 + vB0;
            acc1 += vA1 + vB1;
            acc2 += vA2 + vB2;
            acc3 += vA3 + vB3;
        }
    } else {
        const int i0 = q * 4;
        #pragma unroll
        for (int k = 0; k < 8; k++) {
            int jA = jw * 16 + k, jB = jA + 8;
            float2 bA = zj[jA];
            float2 bB = zj[jB];
            float dx, dy, vA0, vA1, vA2, vA3, vB0, vB1, vB2, vB3;
            dx = ax0 - bA.x; dy = ay0 - bA.y; PHI_NEAR(dx, dy, vA0);
            dx = ax1 - bA.x; dy = ay1 - bA.y; PHI_NEAR(dx, dy, vA1);
            dx = ax2 - bA.x; dy = ay2 - bA.y; PHI_NEAR(dx, dy, vA2);
            dx = ax3 - bA.x; dy = ay3 - bA.y; PHI_NEAR(dx, dy, vA3);
            dx = ax0 - bB.x; dy = ay0 - bB.y; PHI_NEAR(dx, dy, vB0);
            dx = ax1 - bB.x; dy = ay1 - bB.y; PHI_NEAR(dx, dy, vB1);
            dx = ax2 - bB.x; dy = ay2 - bB.y; PHI_NEAR(dx, dy, vB2);
            dx = ax3 - bB.x; dy = ay3 - bB.y; PHI_NEAR(dx, dy, vB3);
            acc0 += ((jA > i0) ? vA0 : 0.f) + ((jB > i0) ? vB0 : 0.f);
            acc1 += ((jA > i0 + 1) ? vA1 : 0.f) + ((jB > i0 + 1) ? vB1 : 0.f);
            acc2 += ((jA > i0 + 2) ? vA2 : 0.f) + ((jB > i0 + 2) ? vB2 : 0.f);
            acc3 += ((jA > i0 + 3) ? vA3 : 0.f) + ((jB > i0 + 3) ? vB3 : 0.f);
        }
    }
    float acc = (acc0 + acc1) + (acc2 + acc3);
    acc = wsum(acc);
    if (l == 0) sRed[w] = (double)acc;
    __syncthreads();
    if (tid == 0) {
        double s = 0;
        for (int i = 0; i < 8; i++) s += sRed[i];
        g_pairp[bid] = s;
        __threadfence();
        unsigned v = atomicAdd(&g_done, 1u);
        sLast = (v == (unsigned)(NTILES - 1));
    }
    __syncthreads();
    if (!sLast) return;
    __threadfence();

    // ---- fused finalize (last block only) ----
    double ps = 0.0;
    for (int i = tid; i < NTILES; i += 256) ps += g_pairp[i];
    double r0 = g_rowp[tid][0] + g_rowp[tid + 256][0];
    double r1 = g_rowp[tid][1] + g_rowp[tid + 256][1];
    double r2 = g_rowp[tid][2] + g_rowp[tid + 256][2];
    double r3 = g_rowp[tid][3] + g_rowp[tid + 256][3];
    double c = 0.0;
    if (tid < 100) {
        int i = tid / 10, j = tid % 10;
        float dx = means[2 * i] - means[2 * j];
        float dy = means[2 * i + 1] - means[2 * j + 1];
        float c1 = dx * dx + dy * dy;
        float vm = vars[i] + vars[j];
        float x = c1 / (2.f * vm + 4.f * gam);
        float c2 = phi_sel(x, K1);
        float c3 = probs[i] * probs[j] * rsqrtf(2.f * (float)M_PI * (vm + 2.f * gam));
        c = (double)(c3 * c2);
    }
    ps = wsumd(ps); r0 = wsumd(r0); r1 = wsumd(r1);
    r2 = wsumd(r2); r3 = wsumd(r3); c = wsumd(c);
    __shared__ double sF[8][6];
    if (l == 0) {
        sF[w][0] = ps; sF[w][1] = r0; sF[w][2] = r1;
        sF[w][3] = r2; sF[w][4] = r3; sF[w][5] = c;
    }
    __syncthreads();
    if (tid == 0) {
        double Ps = 0, Rec = 0, Ce = 0, Bt = 0, Den = 0, Ct = 0;
        for (int i = 0; i < 8; i++) {
            Ps += sF[i][0]; Rec += sF[i][1]; Ce += sF[i][2];
            Bt += sF[i][3]; Den += sF[i][4]; Ct += sF[i][5];
        }
        double m = (double)MROWS;
        double A = (2.0 * Ps + m * phi0) * scaleA;
        double rec = Rec / (m * 64.0);
        if (Den == 0.0) Den = 1.0;
        double cls = Ce / Den;
        double cw = A - Bt + Ct;
        out[0] = (float)(rec + 8.0 + log(cw) + 2.0 * cls);
    }
}

extern "C" void kernel_launch(void* const* d_in, const int* in_sizes, int n_in,
                              void* d_out, int out_size) {
    const float* bd   = (const float*)d_in[0];
    const float* We1  = (const float*)d_in[1];
    const float* be1  = (const float*)d_in[2];
    const float* We2  = (const float*)d_in[3];
    const float* be2  = (const float*)d_in[4];
    const float* We3  = (const float*)d_in[5];
    const float* be3  = (const float*)d_in[6];
    const float* Wd1  = (const float*)d_in[7];
    const float* bd1  = (const float*)d_in[8];
    const float* Wd2  = (const float*)d_in[9];
    const float* bd2  = (const float*)d_in[10];
    const float* Wd3  = (const float*)d_in[11];
    const float* bd3  = (const float*)d_in[12];
    const float* means = (const float*)d_in[13];
    const float* vars  = (const float*)d_in[14];
    const float* probs = (const float*)d_in[15];
    float* out = (float*)d_out;

    const double m = (double)MROWS;
    const double gamma = pow(4.0 / (3.0 * m), 0.2);
    const double pf75 = exp(-3.75) * (1.0 + 3.5156229 + 3.0899424 + 1.2067492 +
                                      0.2659732 + 0.0360768 + 0.0045813);
    const double pg75 = sqrt(2.0 / 7.5) * (0.39894228 + 0.01328592 + 0.00225319 -
                                           0.00157565 + 0.0091628 - 0.02057706 +
                                           0.02635537 - 0.01647633 + 0.00392377);
    const double K1 = pg75 - pf75;
    const double phi0 = 1.0 + K1;
    const double scaleA = 1.0 / (m * m * sqrt(2.0 * M_PI * 2.0 * gamma));
    const float rsc = (float)(1.0 / sqrt(4.0 * gamma));

    k_rows<<<NROWBLK, 256>>>(bd, We1, be1, We2, be2, We3, be3,
                             Wd1, bd1, Wd2, bd2, Wd3, bd3,
                             means, vars, probs, (float)K1, rsc, (float)gamma);
    k_pairs<<<NTILES, 256>>>(means, vars, probs, out,
                             (float)K1, (float)gamma, phi0, scaleA);
}